// round 13
// baseline (speedup 1.0000x reference)
#include <cuda_runtime.h>
#include <cstdint>

// KernelRepeatLinear: out[b,e,j] = bias[j] + sum_k weight[k,j] * P[b, e-7+k, j]
// P[b,e,j] = sum_{i<=j} x[b,e,i] * dv^(j-i)   (decayed inclusive prefix scan over dim)
#define Bv 8
#define Ev 2048
#define Sv 512
#define Kv 8
#define HALO (Kv - 1)
#define TE 16                 // output E-rows per FIR block
#define ROWS (TE + HALO)      // 23 P-rows consumed per FIR block

typedef unsigned long long u64;

// 33.5 MB global scratch for scanned rows P (static __device__ array: allowed)
__device__ float g_P[(size_t)Bv * Ev * Sv];

// packed fp32x2 FMA (Blackwell)
#define FMA_F32X2(d, a, b, c) \
    asm("fma.rn.f32x2 %0, %1, %2, %3;" : "=l"(d) : "l"(a), "l"(b), "l"(c))

// ---------------- Kernel 1: decayed prefix scan, one warp per row -------------
// No smem, no barriers: pure warp-level work, max TLP for latency hiding.
__global__ __launch_bounds__(256, 5)
void krl_scan13(const float* __restrict__ x,
                const float* __restrict__ decay)
{
    const int lane = threadIdx.x & 31;
    const int warp = threadIdx.x >> 5;
    const int row  = blockIdx.x * 8 + warp;       // flattened (b*Ev + e)

    float dv = decay[1];
    dv = fminf(1.0f, fmaxf(0.9f, dv));
    const float dv2 = dv * dv;
    const float dv3 = dv2 * dv;
    const float dv4 = dv2 * dv2;
    const float dv8 = dv4 * dv4;
    const float dv16 = dv8 * dv8;

    const float4* src = (const float4*)(x + (size_t)row * Sv);
    float4 a[4];
    #pragma unroll
    for (int q = 0; q < 4; ++q) a[q] = src[4 * lane + q];   // MLP=4 upfront

    // serial scan of this lane's 16 elements (zero incoming carry)
    float p = 0.f;
    #pragma unroll
    for (int q = 0; q < 4; ++q) {
        p = fmaf(dv, p, a[q].x); a[q].x = p;
        p = fmaf(dv, p, a[q].y); a[q].y = p;
        p = fmaf(dv, p, a[q].z); a[q].z = p;
        p = fmaf(dv, p, a[q].w); a[q].w = p;
    }
    // Kogge-Stone inclusive warp scan of segment ends, hop factor dv^(16*d)
    float s = p;
    float f = dv16;
    #pragma unroll
    for (int d = 1; d < 32; d <<= 1) {
        float o = __shfl_up_sync(0xffffffffu, s, d);
        if (lane >= d) s = fmaf(f, o, s);
        f = f * f;
    }
    float carry = __shfl_up_sync(0xffffffffu, s, 1);
    if (lane == 0) carry = 0.f;

    // apply carry: per-group scalar cq = carry*dv^(4q+1); in-group independent
    float4* dst = (float4*)(g_P + (size_t)row * Sv);
    float cq = carry * dv;
    #pragma unroll
    for (int q = 0; q < 4; ++q) {
        a[q].x = a[q].x + cq;
        a[q].y = fmaf(cq, dv,  a[q].y);
        a[q].z = fmaf(cq, dv2, a[q].z);
        a[q].w = fmaf(cq, dv3, a[q].w);
        dst[4 * lane + q] = a[q];
        cq = cq * dv4;
    }
}

// ---------------- Kernel 2: rolling scatter FIR from L2-resident P ------------
// No smem, no barriers. 8 rotating independent accumulators; P rows streamed
// with prefetch distance 4 to cover L2 latency.
__global__ __launch_bounds__(256, 4)
void krl_fir13(const float* __restrict__ weight,
               const float* __restrict__ bias,
               float* __restrict__ out)
{
    const int jq = threadIdx.x;                    // float2 column, 0..255
    const int blocksPerBatch = Ev / TE;            // 128
    const int b  = blockIdx.x / blocksPerBatch;
    const int t  = blockIdx.x % blocksPerBatch;
    const int e0 = t * TE;

    // weights + bias in registers
    u64 wv[Kv];
    #pragma unroll
    for (int k = 0; k < Kv; ++k)
        wv[k] = ((const u64*)(weight + k * Sv))[jq];
    const u64 bv = ((const u64*)bias)[jq];

    // P row i (i=0..22) = global E-row (e0 - 7 + i); zeros before row 0
    const int gBase = e0 - HALO;                   // may be -7 on first tile
    const u64* Pb = (const u64*)(g_P + ((size_t)b * Ev + gBase) * Sv);

    u64 v[4];
    #pragma unroll
    for (int j = 0; j < 4; ++j)
        v[j] = (gBase + j >= 0) ? Pb[(size_t)j * (Sv / 2) + jq] : 0ull;

    u64* outp = (u64*)(out + ((size_t)b * Ev + e0) * Sv);

    u64 acc[8];
    #pragma unroll
    for (int o = 0; o < 8; ++o) acc[o] = bv;

    #pragma unroll
    for (int i = 0; i < ROWS; ++i) {
        const u64 vcur = v[i & 3];
        // prefetch row i+4 into the slot just freed
        if (i + 4 < ROWS)
            v[i & 3] = (gBase + i + 4 >= 0)
                         ? Pb[(size_t)(i + 4) * (Sv / 2) + jq] : 0ull;
        // scan row i feeds acc[(i-k)&7] for valid taps k
        #pragma unroll
        for (int k = 0; k < 8; ++k) {
            const int o = i - k;
            if (o >= 0 && o < TE)
                FMA_F32X2(acc[o & 7], wv[k], vcur, acc[o & 7]);
        }
        if (i >= HALO) {                           // out row (i-7) complete
            const int o = i - HALO;
            outp[(size_t)o * (Sv / 2) + jq] = acc[o & 7];
            acc[o & 7] = bv;                       // recycle for out row o+8
        }
    }
}

extern "C" void kernel_launch(void* const* d_in, const int* in_sizes, int n_in,
                              void* d_out, int out_size)
{
    const float* x      = (const float*)d_in[0];  // (B, E, S)
    const float* weight = (const float*)d_in[1];  // (K, S)
    const float* bias   = (const float*)d_in[2];  // (S,)
    const float* decay  = (const float*)d_in[3];  // (2, 1)
    float* out          = (float*)d_out;          // (B, E, S)

    krl_scan13<<<Bv * Ev / 8, 256>>>(x, decay);                 // 2048 blocks
    krl_fir13<<<Bv * (Ev / TE), 256>>>(weight, bias, out);      // 1024 blocks
}

// round 14
// speedup vs baseline: 1.1931x; 1.1931x over previous
#include <cuda_runtime.h>
#include <cstdint>

// KernelRepeatLinear: out[b,e,j] = bias[j] + sum_k weight[k,j] * P[b, e-7+k, j]
// P[b,e,j] = sum_{i<=j} x[b,e,i] * dv^(j-i)   (decayed inclusive prefix scan over dim)
#define Bv 8
#define Ev 2048
#define Sv 512
#define Kv 8
#define HALO (Kv - 1)
#define TE 16
#define ROWS (TE + HALO)      // 23 scanned rows (contiguous in gmem)
#define THREADS 256
#define NCHUNK 3              // TMA pipeline chunks: rows [0,8),[8,16),[16,23)

typedef unsigned long long u64;

// packed fp32x2 FMA (Blackwell)
#define FMA_F32X2(d, a, b, c) \
    asm("fma.rn.f32x2 %0, %1, %2, %3;" : "=l"(d) : "l"(a), "l"(b), "l"(c))

__device__ __forceinline__ void mbar_wait_p0(uint32_t addr)
{
    uint32_t done;
    asm volatile(
        "{\n\t.reg .pred p;\n\t"
        "mbarrier.try_wait.parity.acquire.cta.shared::cta.b64 p, [%1], %2;\n\t"
        "selp.b32 %0, 1, 0, p;\n\t}"
        : "=r"(done) : "r"(addr), "r"(0) : "memory");
    if (!done) {
        asm volatile(
            "{\n\t.reg .pred P1;\n\t"
            "WAIT_LOOP_%=:\n\t"
            "mbarrier.try_wait.parity.acquire.cta.shared::cta.b64 P1, [%0], %1, 0x989680;\n\t"
            "@P1 bra.uni WAIT_DONE_%=;\n\t"
            "bra.uni WAIT_LOOP_%=;\n\t"
            "WAIT_DONE_%=:\n\t}"
            :: "r"(addr), "r"(0) : "memory");
    }
}

__global__ __launch_bounds__(THREADS, 4)
void krl_fused14(const float* __restrict__ x,
                 const float* __restrict__ weight,
                 const float* __restrict__ bias,
                 const float* __restrict__ decay,
                 float* __restrict__ out)
{
    __shared__ float shP[ROWS * Sv];                 // 47104 B (x, then P in place)
    __shared__ __align__(8) u64 mbar[NCHUNK];

    const int tid  = threadIdx.x;
    const int lane = tid & 31;
    const int warp = tid >> 5;

    const int blocksPerBatch = Ev / TE;              // 128
    const int b  = blockIdx.x / blocksPerBatch;
    const int t  = blockIdx.x % blocksPerBatch;
    const int e0 = t * TE;

    const float* xb = x + (size_t)b * Ev * Sv;

    uint32_t mbar_addr, shP_addr;
    {
        uint64_t tmp;
        asm("cvta.to.shared.u64 %0, %1;" : "=l"(tmp) : "l"(&mbar[0]));
        mbar_addr = (uint32_t)tmp;
        asm("cvta.to.shared.u64 %0, %1;" : "=l"(tmp) : "l"(shP));
        shP_addr = (uint32_t)tmp;
    }

    const int gFirstWanted = e0 - HALO;              // may be -7 on first tile
    const int dstRow = (gFirstWanted < 0) ? -gFirstWanted : 0;   // 7 on first tile

    // init chunk barriers; zero halo rows (first tile only) before the sync
    if (tid < NCHUNK)
        asm volatile("mbarrier.init.shared.b64 [%0], %1;"
                     :: "r"(mbar_addr + 8u * tid), "r"(1) : "memory");
    if (dstRow != 0) {
        float4* z = (float4*)shP;
        for (int i = tid; i < dstRow * (Sv / 4); i += THREADS)
            z[i] = make_float4(0.f, 0.f, 0.f, 0.f);
    }
    __syncthreads();   // barriers initialized + halo zeros visible

    // ---- pipelined chunked TMA: rows [0,8),[8,16),[16,23) of the scan tile ----
    if (tid == 0) {
        #pragma unroll
        for (int c = 0; c < NCHUNK; ++c) {
            const int lo = (8 * c > dstRow) ? 8 * c : dstRow;   // skip halo rows
            const int hi = (8 * c + 8 < ROWS) ? 8 * c + 8 : ROWS;
            const uint32_t bytes = (uint32_t)(hi - lo) * Sv * 4u;
            const uint32_t ba = mbar_addr + 8u * c;
            asm volatile("mbarrier.arrive.expect_tx.shared.b64 _, [%0], %1;"
                         :: "r"(ba), "r"(bytes) : "memory");
            asm volatile("cp.async.bulk.shared::cta.global.mbarrier::complete_tx::bytes "
                         "[%0], [%1], %2, [%3];"
                         :: "r"(shP_addr + (uint32_t)lo * Sv * 4u),
                            "l"(xb + (size_t)(gFirstWanted + lo) * Sv),
                            "r"(bytes), "r"(ba) : "memory");
        }
    }

    float dv = decay[1];
    dv = fminf(1.0f, fmaxf(0.9f, dv));
    const float dv2 = dv * dv;
    const float dv3 = dv2 * dv;
    const float dv4 = dv2 * dv2;
    const float dv8 = dv4 * dv4;
    const float dv16 = dv8 * dv8;

    // hoist weight/bias LDGs: latency hides behind the chunk waits
    const int jq = tid;                               // float2 column, 0..255
    u64 wv[Kv];
    #pragma unroll
    for (int k = 0; k < Kv; ++k)
        wv[k] = ((const u64*)(weight + k * Sv))[jq];
    const u64 bv = ((const u64*)bias)[jq];

    // -------- Phase 1: scan rows as their chunk arrives (staggered waits) ------
    #pragma unroll
    for (int it = 0; it < 3; ++it) {
        const int r = warp + 8 * it;                  // row = chunk it, warp lane
        if (r >= ROWS) break;                         // it=2 only warps 0..6
        mbar_wait_p0(mbar_addr + 8u * it);            // wait this row's chunk

        float4* rowp = (float4*)(shP + r * Sv);
        float4 a[4];
        #pragma unroll
        for (int q = 0; q < 4; ++q) a[q] = rowp[4 * lane + q];

        float p = 0.f;
        #pragma unroll
        for (int q = 0; q < 4; ++q) {
            p = fmaf(dv, p, a[q].x); a[q].x = p;
            p = fmaf(dv, p, a[q].y); a[q].y = p;
            p = fmaf(dv, p, a[q].z); a[q].z = p;
            p = fmaf(dv, p, a[q].w); a[q].w = p;
        }
        float s = p;
        float f = dv16;
        #pragma unroll
        for (int d = 1; d < 32; d <<= 1) {
            float o = __shfl_up_sync(0xffffffffu, s, d);
            if (lane >= d) s = fmaf(f, o, s);
            f = f * f;
        }
        float carry = __shfl_up_sync(0xffffffffu, s, 1);
        if (lane == 0) carry = 0.f;

        float cq = carry * dv;                        // carry * dv^(4q+1)
        #pragma unroll
        for (int q = 0; q < 4; ++q) {
            a[q].x = a[q].x + cq;
            a[q].y = fmaf(cq, dv,  a[q].y);
            a[q].z = fmaf(cq, dv2, a[q].z);
            a[q].w = fmaf(cq, dv3, a[q].w);
            rowp[4 * lane + q] = a[q];
            cq = cq * dv4;
        }
    }
    __syncthreads();

    // -------- Phase 2: rolling scatter FIR, 8 rotating independent accs -------
    u64* outp = (u64*)(out + ((size_t)b * Ev + e0) * Sv);

    u64 acc[8];
    #pragma unroll
    for (int o = 0; o < 8; ++o) acc[o] = bv;

    u64 vcur = ((const u64*)shP)[jq];
    #pragma unroll
    for (int i = 0; i < ROWS; ++i) {
        u64 vnext = 0ull;
        if (i < ROWS - 1)
            vnext = ((const u64*)(shP + (i + 1) * Sv))[jq];
        #pragma unroll
        for (int k = 0; k < 8; ++k) {
            const int o = i - k;
            if (o >= 0 && o < TE)
                FMA_F32X2(acc[o & 7], wv[k], vcur, acc[o & 7]);
        }
        if (i >= HALO) {                              // out row (i-7) complete
            const int o = i - HALO;
            outp[(size_t)o * (Sv / 2) + jq] = acc[o & 7];
            acc[o & 7] = bv;                          // recycle for out row o+8
        }
        vcur = vnext;
    }
}

extern "C" void kernel_launch(void* const* d_in, const int* in_sizes, int n_in,
                              void* d_out, int out_size)
{
    const float* x      = (const float*)d_in[0];  // (B, E, S)
    const float* weight = (const float*)d_in[1];  // (K, S)
    const float* bias   = (const float*)d_in[2];  // (S,)
    const float* decay  = (const float*)d_in[3];  // (2, 1)
    float* out          = (float*)d_out;          // (B, E, S)

    krl_fused14<<<Bv * (Ev / TE), THREADS>>>(x, weight, bias, decay, out);
}